// round 1
// baseline (speedup 1.0000x reference)
#include <cuda_runtime.h>
#include <cstdint>

#define NUM_USERS 100000
#define NUM_ITEMS 50000
#define DIM 64
#define NUM_REL 5

// Scratch: per-item transformed features Ti[item][r][k] (64 MB) and bias dots.
__device__ float g_Ti[(size_t)NUM_ITEMS * NUM_REL * DIM];   // 64 MB
__device__ float g_bi[(size_t)NUM_ITEMS * 8];               // padded stride 8
__device__ int   g_idx64;                                   // 1 if indices are int64

// ---------------------------------------------------------------------------
// Detect index dtype: if int64, every odd 32-bit word is a zero high-word.
// ---------------------------------------------------------------------------
__global__ void detect_idx_kernel(const void* eu) {
    const int* p = (const int*)eu;
    int is64 = 1;
    #pragma unroll
    for (int j = 1; j < 16; j += 2) {
        if (p[j] != 0) is64 = 0;
    }
    g_idx64 = is64;
}

// ---------------------------------------------------------------------------
// Precompute: Ti[item][r][k] = sum_d i[item,d] * W[r][d][k]
//             bi[item][r]    = sum_d b[r,d]    * i[item,d]
// One thread per item; W[r] staged in shared memory (broadcast LDS).
// ---------------------------------------------------------------------------
__global__ void precompute_kernel(const float* __restrict__ ifeat,
                                  const float* __restrict__ W,
                                  const float* __restrict__ b) {
    __shared__ float Ws[DIM * DIM];
    int item = blockIdx.x * blockDim.x + threadIdx.x;

    for (int r = 0; r < NUM_REL; r++) {
        __syncthreads();
        for (int t = threadIdx.x; t < DIM * DIM / 4; t += blockDim.x)
            ((float4*)Ws)[t] = ((const float4*)(W + (size_t)r * DIM * DIM))[t];
        __syncthreads();

        if (item < NUM_ITEMS) {
            float acc[DIM];
            #pragma unroll
            for (int k = 0; k < DIM; k++) acc[k] = 0.0f;
            float bacc = 0.0f;
            const float* irow = ifeat + (size_t)item * DIM;
            const float* brow = b + (size_t)r * DIM;

            for (int d = 0; d < DIM; d++) {
                float id = __ldg(irow + d);
                bacc += id * __ldg(brow + d);
                const float4* wr = (const float4*)(Ws + d * DIM);
                #pragma unroll
                for (int j = 0; j < DIM / 4; j++) {
                    float4 w = wr[j];
                    acc[4 * j + 0] += id * w.x;
                    acc[4 * j + 1] += id * w.y;
                    acc[4 * j + 2] += id * w.z;
                    acc[4 * j + 3] += id * w.w;
                }
            }

            float4* op = (float4*)(g_Ti + ((size_t)item * NUM_REL + r) * DIM);
            #pragma unroll
            for (int j = 0; j < DIM / 4; j++)
                op[j] = make_float4(acc[4 * j], acc[4 * j + 1],
                                    acc[4 * j + 2], acc[4 * j + 3]);
            g_bi[(size_t)item * 8 + r] = bacc;
        }
    }
}

// ---------------------------------------------------------------------------
// Edge kernel: 16 lanes per edge.
// out[e][r] = dot(u_feat[user], Ti[item][r]) + bi[item][r]
// ---------------------------------------------------------------------------
__global__ void edge_kernel(const float* __restrict__ ufeat,
                            const void* __restrict__ edge_u,
                            const void* __restrict__ edge_i,
                            float* __restrict__ out,
                            int E) {
    int gid = blockIdx.x * blockDim.x + threadIdx.x;
    int e  = gid >> 4;
    int sl = gid & 15;
    if (e >= E) return;

    long long user, item;
    if (g_idx64) {
        user = __ldg((const long long*)edge_u + e);
        item = __ldg((const long long*)edge_i + e);
    } else {
        user = (long long)__ldg((const int*)edge_u + e);
        item = (long long)__ldg((const int*)edge_i + e);
    }

    float4 uv = __ldg((const float4*)ufeat + (size_t)user * (DIM / 4) + sl);
    const float4* trow = (const float4*)(g_Ti + (size_t)item * NUM_REL * DIM);

    float a0, a1, a2, a3, a4;
    {
        float4 t;
        t = trow[0 * 16 + sl]; a0 = uv.x * t.x + uv.y * t.y + uv.z * t.z + uv.w * t.w;
        t = trow[1 * 16 + sl]; a1 = uv.x * t.x + uv.y * t.y + uv.z * t.z + uv.w * t.w;
        t = trow[2 * 16 + sl]; a2 = uv.x * t.x + uv.y * t.y + uv.z * t.z + uv.w * t.w;
        t = trow[3 * 16 + sl]; a3 = uv.x * t.x + uv.y * t.y + uv.z * t.z + uv.w * t.w;
        t = trow[4 * 16 + sl]; a4 = uv.x * t.x + uv.y * t.y + uv.z * t.z + uv.w * t.w;
    }

    // Butterfly reduce within the 16-lane group (laneMask <= 8 stays in-group).
    #pragma unroll
    for (int off = 8; off > 0; off >>= 1) {
        a0 += __shfl_xor_sync(0xffffffffu, a0, off);
        a1 += __shfl_xor_sync(0xffffffffu, a1, off);
        a2 += __shfl_xor_sync(0xffffffffu, a2, off);
        a3 += __shfl_xor_sync(0xffffffffu, a3, off);
        a4 += __shfl_xor_sync(0xffffffffu, a4, off);
    }

    if (sl < NUM_REL) {
        float v = (sl == 0) ? a0 : (sl == 1) ? a1 : (sl == 2) ? a2
                : (sl == 3) ? a3 : a4;
        v += __ldg(g_bi + (size_t)item * 8 + sl);
        out[(size_t)e * NUM_REL + sl] = v;
    }
}

// ---------------------------------------------------------------------------
extern "C" void kernel_launch(void* const* d_in, const int* in_sizes, int n_in,
                              void* d_out, int out_size) {
    const float* uf  = (const float*)d_in[0];
    const float* itf = (const float*)d_in[1];
    const void*  eu  = d_in[2];
    const void*  ei  = d_in[3];
    const float* W   = (const float*)d_in[4];
    const float* b   = (const float*)d_in[5];
    int E = in_sizes[2];

    detect_idx_kernel<<<1, 1>>>(eu);

    int pthreads = 128;
    int pblocks = (NUM_ITEMS + pthreads - 1) / pthreads;
    precompute_kernel<<<pblocks, pthreads>>>(itf, W, b);

    long long total_threads = (long long)E * 16;
    int eblocks = (int)((total_threads + 255) / 256);
    edge_kernel<<<eblocks, 256>>>(uf, eu, ei, (float*)d_out, E);
}

// round 2
// speedup vs baseline: 1.3084x; 1.3084x over previous
#include <cuda_runtime.h>
#include <cuda_fp16.h>
#include <cstdint>

#define NUM_USERS 100000
#define NUM_ITEMS 50000
#define DIM 64
#define NUM_REL 5

// Scratch: fp16 transformed item features (32 MB), fp16 user copy (12.8 MB),
// fp32 bias dots, index-width flag.
__device__ __half g_Ti[(size_t)NUM_ITEMS * NUM_REL * DIM];  // 32 MB
__device__ __half g_uh[(size_t)NUM_USERS * DIM];            // 12.8 MB
__device__ float  g_bi[(size_t)NUM_ITEMS * 8];              // stride 8
__device__ int    g_idx64;

// ---------------------------------------------------------------------------
// Detect index dtype: int64 indices (< 2^31) have zero odd 32-bit words.
// ---------------------------------------------------------------------------
__global__ void detect_idx_kernel(const void* eu) {
    const int* p = (const int*)eu;
    int is64 = 1;
    #pragma unroll
    for (int j = 1; j < 16; j += 2)
        if (p[j] != 0) is64 = 0;
    g_idx64 = is64;
}

// ---------------------------------------------------------------------------
// Convert user features to fp16.
// ---------------------------------------------------------------------------
__global__ void uconv_kernel(const float* __restrict__ uf) {
    size_t i = (size_t)blockIdx.x * blockDim.x + threadIdx.x;   // half2 index
    size_t n = (size_t)NUM_USERS * DIM / 2;
    if (i < n) {
        float2 v = ((const float2*)uf)[i];
        ((__half2*)g_uh)[i] = __floats2half2_rn(v.x, v.y);
    }
}

// ---------------------------------------------------------------------------
// Precompute: Ti[item][r][k] = sum_d i[item,d] * W[r][d][k]   (stored fp16)
//             bi[item][r]    = sum_d b[r,d]    * i[item,d]    (fp32)
// One thread per item; W[r] staged in shared memory (broadcast LDS).
// ---------------------------------------------------------------------------
__global__ void precompute_kernel(const float* __restrict__ ifeat,
                                  const float* __restrict__ W,
                                  const float* __restrict__ b) {
    __shared__ float Ws[DIM * DIM];
    int item = blockIdx.x * blockDim.x + threadIdx.x;

    for (int r = 0; r < NUM_REL; r++) {
        __syncthreads();
        for (int t = threadIdx.x; t < DIM * DIM / 4; t += blockDim.x)
            ((float4*)Ws)[t] = ((const float4*)(W + (size_t)r * DIM * DIM))[t];
        __syncthreads();

        if (item < NUM_ITEMS) {
            float acc[DIM];
            #pragma unroll
            for (int k = 0; k < DIM; k++) acc[k] = 0.0f;
            float bacc = 0.0f;
            const float* irow = ifeat + (size_t)item * DIM;
            const float* brow = b + (size_t)r * DIM;

            for (int d = 0; d < DIM; d++) {
                float id = __ldg(irow + d);
                bacc = fmaf(id, __ldg(brow + d), bacc);
                const float4* wr = (const float4*)(Ws + d * DIM);
                #pragma unroll
                for (int j = 0; j < DIM / 4; j++) {
                    float4 w = wr[j];
                    acc[4 * j + 0] = fmaf(id, w.x, acc[4 * j + 0]);
                    acc[4 * j + 1] = fmaf(id, w.y, acc[4 * j + 1]);
                    acc[4 * j + 2] = fmaf(id, w.z, acc[4 * j + 2]);
                    acc[4 * j + 3] = fmaf(id, w.w, acc[4 * j + 3]);
                }
            }

            __half2* op = (__half2*)(g_Ti + ((size_t)item * NUM_REL + r) * DIM);
            #pragma unroll
            for (int j = 0; j < DIM / 2; j++)
                op[j] = __floats2half2_rn(acc[2 * j], acc[2 * j + 1]);
            g_bi[(size_t)item * 8 + r] = bacc;
        }
    }
}

// ---------------------------------------------------------------------------
// Edge kernel: 8 lanes per edge, each lane owns 8 halves (one uint4).
// out[e][r] = dot(u[user], Ti[item][r]) + bi[item][r]
// ---------------------------------------------------------------------------
__device__ __forceinline__ float dot8h(uint4 a, uint4 b) {
    float2 a0 = __half22float2(*(const __half2*)&a.x);
    float2 b0 = __half22float2(*(const __half2*)&b.x);
    float2 a1 = __half22float2(*(const __half2*)&a.y);
    float2 b1 = __half22float2(*(const __half2*)&b.y);
    float2 a2 = __half22float2(*(const __half2*)&a.z);
    float2 b2 = __half22float2(*(const __half2*)&b.z);
    float2 a3 = __half22float2(*(const __half2*)&a.w);
    float2 b3 = __half22float2(*(const __half2*)&b.w);
    float s = a0.x * b0.x;
    s = fmaf(a0.y, b0.y, s);
    s = fmaf(a1.x, b1.x, s);
    s = fmaf(a1.y, b1.y, s);
    s = fmaf(a2.x, b2.x, s);
    s = fmaf(a2.y, b2.y, s);
    s = fmaf(a3.x, b3.x, s);
    s = fmaf(a3.y, b3.y, s);
    return s;
}

__global__ void edge_kernel(const void* __restrict__ edge_u,
                            const void* __restrict__ edge_i,
                            float* __restrict__ out,
                            int E) {
    int gid = blockIdx.x * blockDim.x + threadIdx.x;
    int e  = gid >> 3;
    int sl = gid & 7;
    if (e >= E) return;

    long long user, item;
    if (g_idx64) {
        user = __ldg((const long long*)edge_u + e);
        item = __ldg((const long long*)edge_i + e);
    } else {
        user = (long long)__ldg((const int*)edge_u + e);
        item = (long long)__ldg((const int*)edge_i + e);
    }

    // u row = 64 halves = 8 uint4; lane sl takes the sl-th uint4.
    uint4 uv = __ldg((const uint4*)g_uh + (size_t)user * 8 + sl);
    const uint4* trow = (const uint4*)g_Ti + (size_t)item * (NUM_REL * 8);

    float a0 = dot8h(uv, __ldg(trow + 0 * 8 + sl));
    float a1 = dot8h(uv, __ldg(trow + 1 * 8 + sl));
    float a2 = dot8h(uv, __ldg(trow + 2 * 8 + sl));
    float a3 = dot8h(uv, __ldg(trow + 3 * 8 + sl));
    float a4 = dot8h(uv, __ldg(trow + 4 * 8 + sl));

    // Reduce within the 8-lane group.
    #pragma unroll
    for (int off = 4; off > 0; off >>= 1) {
        a0 += __shfl_xor_sync(0xffffffffu, a0, off);
        a1 += __shfl_xor_sync(0xffffffffu, a1, off);
        a2 += __shfl_xor_sync(0xffffffffu, a2, off);
        a3 += __shfl_xor_sync(0xffffffffu, a3, off);
        a4 += __shfl_xor_sync(0xffffffffu, a4, off);
    }

    if (sl < NUM_REL) {
        float v = (sl == 0) ? a0 : (sl == 1) ? a1 : (sl == 2) ? a2
                : (sl == 3) ? a3 : a4;
        v += __ldg(g_bi + (size_t)item * 8 + sl);
        out[(size_t)e * NUM_REL + sl] = v;
    }
}

// ---------------------------------------------------------------------------
extern "C" void kernel_launch(void* const* d_in, const int* in_sizes, int n_in,
                              void* d_out, int out_size) {
    const float* uf  = (const float*)d_in[0];
    const float* itf = (const float*)d_in[1];
    const void*  eu  = d_in[2];
    const void*  ei  = d_in[3];
    const float* W   = (const float*)d_in[4];
    const float* b   = (const float*)d_in[5];
    int E = in_sizes[2];

    detect_idx_kernel<<<1, 1>>>(eu);

    {
        size_t n = (size_t)NUM_USERS * DIM / 2;
        uconv_kernel<<<(unsigned)((n + 255) / 256), 256>>>(uf);
    }

    int pthreads = 128;
    int pblocks = (NUM_ITEMS + pthreads - 1) / pthreads;
    precompute_kernel<<<pblocks, pthreads>>>(itf, W, b);

    long long total_threads = (long long)E * 8;
    int eblocks = (int)((total_threads + 255) / 256);
    edge_kernel<<<eblocks, 256>>>(eu, ei, (float*)d_out, E);
}

// round 3
// speedup vs baseline: 1.7028x; 1.3015x over previous
#include <cuda_runtime.h>
#include <cuda_fp16.h>
#include <cstdint>

#define NUM_USERS 100000
#define NUM_ITEMS 50000
#define DIM 64
#define NUM_REL 5

typedef unsigned long long ull;

// Scratch: fp16 transformed item features (32 MB), fp16 user copy (12.8 MB),
// fp32 bias dots, index-width flag.
__device__ __half g_Ti[(size_t)NUM_ITEMS * NUM_REL * DIM];  // 32 MB
__device__ __half g_uh[(size_t)NUM_USERS * DIM];            // 12.8 MB
__device__ float  g_bi[(size_t)NUM_ITEMS * 8];              // stride 8
__device__ int    g_idx64;

// ---------------------------------------------------------------------------
// Packed f32x2 FMA (Blackwell): d = a * b + d  on two floats at once.
// ---------------------------------------------------------------------------
__device__ __forceinline__ void fma2(ull& d, ull a, ull b) {
    asm("fma.rn.f32x2 %0, %1, %2, %0;" : "+l"(d) : "l"(a), "l"(b));
}
__device__ __forceinline__ ull dup2(float v) {
    ull p;
    asm("mov.b64 %0, {%1, %1};" : "=l"(p) : "f"(v));
    return p;
}
__device__ __forceinline__ float2 unpack2(ull p) {
    float2 r;
    asm("mov.b64 {%0, %1}, %2;" : "=f"(r.x), "=f"(r.y) : "l"(p));
    return r;
}

// ---------------------------------------------------------------------------
// Detect index dtype: int64 indices (< 2^31) have zero odd 32-bit words.
// ---------------------------------------------------------------------------
__global__ void detect_idx_kernel(const void* eu) {
    const int* p = (const int*)eu;
    int is64 = 1;
    #pragma unroll
    for (int j = 1; j < 16; j += 2)
        if (p[j] != 0) is64 = 0;
    g_idx64 = is64;
}

// ---------------------------------------------------------------------------
// Convert user features to fp16.
// ---------------------------------------------------------------------------
__global__ void uconv_kernel(const float* __restrict__ uf) {
    size_t i = (size_t)blockIdx.x * blockDim.x + threadIdx.x;   // half2 index
    size_t n = (size_t)NUM_USERS * DIM / 2;
    if (i < n) {
        float2 v = ((const float2*)uf)[i];
        ((__half2*)g_uh)[i] = __floats2half2_rn(v.x, v.y);
    }
}

// ---------------------------------------------------------------------------
// bi[item][r] = sum_d b[r,d] * i[item,d]   (one thread per (item, r))
// ---------------------------------------------------------------------------
__global__ void bi_kernel(const float* __restrict__ ifeat,
                          const float* __restrict__ b) {
    int t = blockIdx.x * blockDim.x + threadIdx.x;
    if (t >= NUM_ITEMS * NUM_REL) return;
    int item = t / NUM_REL;
    int r    = t - item * NUM_REL;
    const float* irow = ifeat + (size_t)item * DIM;
    const float* brow = b + (size_t)r * DIM;
    float s = 0.0f;
    #pragma unroll 16
    for (int d = 0; d < DIM; d++)
        s = fmaf(__ldg(irow + d), __ldg(brow + d), s);
    g_bi[(size_t)item * 8 + r] = s;
}

// ---------------------------------------------------------------------------
// Precompute Ti as a register-tiled GEMM with packed f32x2 FMA.
//   Ti[item][r][k] = sum_d i[item,d] * W[r][d][k]   (stored fp16)
// Block: 256 threads, tile = 64 items x 64 cols per relation.
// Thread (g, c): items 4g..4g+3, cols 4c..4c+3 (16 fp32 accs as 8 f32x2).
// ---------------------------------------------------------------------------
#define TILE_ITEMS 64
__global__ __launch_bounds__(256) void precompute_kernel(
        const float* __restrict__ ifeat,
        const float* __restrict__ W) {
    __shared__ ull   As2[TILE_ITEMS * DIM];   // duplicated {a,a} pairs, 32 KB
    __shared__ float Ws[DIM * DIM];           // one relation's W, 16 KB

    int tid   = threadIdx.x;
    int item0 = blockIdx.x * TILE_ITEMS;
    int c = tid & 15;   // col group: cols 4c..4c+3
    int g = tid >> 4;   // item group: items 4g..4g+3

    // Stage item features (duplicated pairs). Clamp OOB items to a valid row.
    for (int idx = tid; idx < TILE_ITEMS * DIM; idx += 256) {
        int it = idx >> 6, d = idx & 63;
        int gi = item0 + it;
        if (gi >= NUM_ITEMS) gi = NUM_ITEMS - 1;
        As2[idx] = dup2(__ldg(ifeat + (size_t)gi * DIM + d));
    }

    for (int r = 0; r < NUM_REL; r++) {
        __syncthreads();   // also covers As2 visibility on first iteration
        for (int idx = tid; idx < DIM * DIM / 4; idx += 256)
            ((float4*)Ws)[idx] =
                __ldg((const float4*)(W + (size_t)r * DIM * DIM) + idx);
        __syncthreads();

        ull acc[4][2] = {};
        #pragma unroll 8
        for (int d = 0; d < DIM; d++) {
            // W[d][4c..4c+3] as two packed f32x2 (one LDS.128)
            ulonglong2 w = *(const ulonglong2*)(Ws + d * DIM + c * 4);
            #pragma unroll
            for (int i = 0; i < 4; i++) {
                ull a2 = As2[(g * 4 + i) * DIM + d];   // broadcast within warp
                fma2(acc[i][0], a2, w.x);
                fma2(acc[i][1], a2, w.y);
            }
        }

        #pragma unroll
        for (int i = 0; i < 4; i++) {
            int gi = item0 + g * 4 + i;
            if (gi < NUM_ITEMS) {
                float2 p0 = unpack2(acc[i][0]);
                float2 p1 = unpack2(acc[i][1]);
                __half2 h0 = __floats2half2_rn(p0.x, p0.y);
                __half2 h1 = __floats2half2_rn(p1.x, p1.y);
                uint2 st;
                st.x = *(unsigned int*)&h0;
                st.y = *(unsigned int*)&h1;
                *(uint2*)(g_Ti + ((size_t)gi * NUM_REL + r) * DIM + c * 4) = st;
            }
        }
    }
}

// ---------------------------------------------------------------------------
// Edge kernel: 8 lanes per edge, each lane owns 8 halves (one uint4).
// out[e][r] = dot(u[user], Ti[item][r]) + bi[item][r]
// ---------------------------------------------------------------------------
__device__ __forceinline__ float dot8h(uint4 a, uint4 b) {
    float2 a0 = __half22float2(*(const __half2*)&a.x);
    float2 b0 = __half22float2(*(const __half2*)&b.x);
    float2 a1 = __half22float2(*(const __half2*)&a.y);
    float2 b1 = __half22float2(*(const __half2*)&b.y);
    float2 a2 = __half22float2(*(const __half2*)&a.z);
    float2 b2 = __half22float2(*(const __half2*)&b.z);
    float2 a3 = __half22float2(*(const __half2*)&a.w);
    float2 b3 = __half22float2(*(const __half2*)&b.w);
    float s = a0.x * b0.x;
    s = fmaf(a0.y, b0.y, s);
    s = fmaf(a1.x, b1.x, s);
    s = fmaf(a1.y, b1.y, s);
    s = fmaf(a2.x, b2.x, s);
    s = fmaf(a2.y, b2.y, s);
    s = fmaf(a3.x, b3.x, s);
    s = fmaf(a3.y, b3.y, s);
    return s;
}

__global__ void edge_kernel(const void* __restrict__ edge_u,
                            const void* __restrict__ edge_i,
                            float* __restrict__ out,
                            int E) {
    int gid = blockIdx.x * blockDim.x + threadIdx.x;
    int e  = gid >> 3;
    int sl = gid & 7;
    if (e >= E) return;

    long long user, item;
    if (g_idx64) {
        user = __ldg((const long long*)edge_u + e);
        item = __ldg((const long long*)edge_i + e);
    } else {
        user = (long long)__ldg((const int*)edge_u + e);
        item = (long long)__ldg((const int*)edge_i + e);
    }

    uint4 uv = __ldg((const uint4*)g_uh + (size_t)user * 8 + sl);
    const uint4* trow = (const uint4*)g_Ti + (size_t)item * (NUM_REL * 8);

    float a0 = dot8h(uv, __ldg(trow + 0 * 8 + sl));
    float a1 = dot8h(uv, __ldg(trow + 1 * 8 + sl));
    float a2 = dot8h(uv, __ldg(trow + 2 * 8 + sl));
    float a3 = dot8h(uv, __ldg(trow + 3 * 8 + sl));
    float a4 = dot8h(uv, __ldg(trow + 4 * 8 + sl));

    #pragma unroll
    for (int off = 4; off > 0; off >>= 1) {
        a0 += __shfl_xor_sync(0xffffffffu, a0, off);
        a1 += __shfl_xor_sync(0xffffffffu, a1, off);
        a2 += __shfl_xor_sync(0xffffffffu, a2, off);
        a3 += __shfl_xor_sync(0xffffffffu, a3, off);
        a4 += __shfl_xor_sync(0xffffffffu, a4, off);
    }

    if (sl < NUM_REL) {
        float v = (sl == 0) ? a0 : (sl == 1) ? a1 : (sl == 2) ? a2
                : (sl == 3) ? a3 : a4;
        v += __ldg(g_bi + (size_t)item * 8 + sl);
        out[(size_t)e * NUM_REL + sl] = v;
    }
}

// ---------------------------------------------------------------------------
extern "C" void kernel_launch(void* const* d_in, const int* in_sizes, int n_in,
                              void* d_out, int out_size) {
    const float* uf  = (const float*)d_in[0];
    const float* itf = (const float*)d_in[1];
    const void*  eu  = d_in[2];
    const void*  ei  = d_in[3];
    const float* W   = (const float*)d_in[4];
    const float* b   = (const float*)d_in[5];
    int E = in_sizes[2];

    detect_idx_kernel<<<1, 1>>>(eu);

    {
        size_t n = (size_t)NUM_USERS * DIM / 2;
        uconv_kernel<<<(unsigned)((n + 255) / 256), 256>>>(uf);
    }

    {
        int n = NUM_ITEMS * NUM_REL;
        bi_kernel<<<(n + 255) / 256, 256>>>(itf, b);
    }

    {
        int blocks = (NUM_ITEMS + TILE_ITEMS - 1) / TILE_ITEMS;
        precompute_kernel<<<blocks, 256>>>(itf, W);
    }

    long long total_threads = (long long)E * 8;
    int eblocks = (int)((total_threads + 255) / 256);
    edge_kernel<<<eblocks, 256>>>(eu, ei, (float*)d_out, E);
}

// round 4
// speedup vs baseline: 1.7889x; 1.0506x over previous
#include <cuda_runtime.h>
#include <cuda_fp16.h>
#include <cstdint>

#define NUM_USERS 100000
#define NUM_ITEMS 50000
#define DIM 64
#define NUM_REL 5

typedef unsigned long long ull;

__device__ __half g_Ti[(size_t)NUM_ITEMS * NUM_REL * DIM];  // 32 MB
__device__ __half g_uh[(size_t)NUM_USERS * DIM];            // 12.8 MB
__device__ float  g_bi[(size_t)NUM_ITEMS * 8];              // stride 8
__device__ int    g_idx64;

// ---------------------------------------------------------------------------
// Packed f32x2 FMA (Blackwell): d = a * b + d  on two floats at once.
// ---------------------------------------------------------------------------
__device__ __forceinline__ void fma2(ull& d, ull a, ull b) {
    asm("fma.rn.f32x2 %0, %1, %2, %0;" : "+l"(d) : "l"(a), "l"(b));
}
__device__ __forceinline__ ull dup2(float v) {
    ull p;
    asm("mov.b64 %0, {%1, %1};" : "=l"(p) : "f"(v));
    return p;
}
__device__ __forceinline__ float2 unpack2(ull p) {
    float2 r;
    asm("mov.b64 {%0, %1}, %2;" : "=f"(r.x), "=f"(r.y) : "l"(p));
    return r;
}

// ---------------------------------------------------------------------------
// Convert user features to fp16; block 0 thread 0 also detects index width.
// ---------------------------------------------------------------------------
__global__ void uconv_kernel(const float* __restrict__ uf,
                             const void* __restrict__ eu) {
    if (blockIdx.x == 0 && threadIdx.x == 0) {
        const int* p = (const int*)eu;
        int is64 = 1;
        #pragma unroll
        for (int j = 1; j < 16; j += 2)
            if (p[j] != 0) is64 = 0;
        g_idx64 = is64;
    }
    size_t i = (size_t)blockIdx.x * blockDim.x + threadIdx.x;   // half2 index
    size_t n = (size_t)NUM_USERS * DIM / 2;
    if (i < n) {
        float2 v = ((const float2*)uf)[i];
        ((__half2*)g_uh)[i] = __floats2half2_rn(v.x, v.y);
    }
}

// ---------------------------------------------------------------------------
// Precompute Ti (register-tiled GEMM, f32x2 FMA, d-pair LDS.128 A loads)
//   Ti[item][r][k] = sum_d i[item,d] * W[r][d][k]   (stored fp16)
//   bi[item][r]    = sum_d b[r,d] * i[item,d]       (fused here)
// Block: 256 threads; tile = 64 items x 64 cols per relation.
// Thread (g = tid>>4, c = tid&15): items 4g..4g+3, cols 4c..4c+3.
// ---------------------------------------------------------------------------
#define TILE_ITEMS 64
__global__ __launch_bounds__(256) void precompute_kernel(
        const float* __restrict__ ifeat,
        const float* __restrict__ W,
        const float* __restrict__ b) {
    __shared__ ull   As2[TILE_ITEMS * DIM];   // duplicated {a,a} pairs, 32 KB
    __shared__ float Ws[DIM * DIM];           // one relation's W, 16 KB

    int tid   = threadIdx.x;
    int item0 = blockIdx.x * TILE_ITEMS;
    int c = tid & 15;   // col group: cols 4c..4c+3
    int g = tid >> 4;   // item group: items 4g..4g+3 (constant per half-warp)

    // Stage item features as duplicated pairs, d contiguous per item.
    for (int idx = tid; idx < TILE_ITEMS * DIM; idx += 256) {
        int it = idx >> 6, d = idx & 63;
        int gi = item0 + it;
        if (gi >= NUM_ITEMS) gi = NUM_ITEMS - 1;
        As2[idx] = dup2(__ldg(ifeat + (size_t)gi * DIM + d));
    }
    __syncthreads();

    // Fused bi: 320 (item, rel) dots per block over 256 threads.
    for (int idx = tid; idx < TILE_ITEMS * NUM_REL; idx += 256) {
        int it = idx / NUM_REL;
        int r  = idx - it * NUM_REL;
        int gi = item0 + it;
        if (gi < NUM_ITEMS) {
            const float* brow = b + (size_t)r * DIM;
            float s = 0.0f;
            #pragma unroll 16
            for (int d = 0; d < DIM; d++) {
                float2 a = unpack2(As2[it * DIM + d]);
                s = fmaf(a.x, __ldg(brow + d), s);
            }
            g_bi[(size_t)gi * 8 + r] = s;
        }
    }

    for (int r = 0; r < NUM_REL; r++) {
        __syncthreads();
        for (int idx = tid; idx < DIM * DIM / 4; idx += 256)
            ((float4*)Ws)[idx] =
                __ldg((const float4*)(W + (size_t)r * DIM * DIM) + idx);
        __syncthreads();

        ull acc[4][2] = {};
        #pragma unroll 4
        for (int d = 0; d < DIM; d += 2) {
            // W rows d, d+1 cols 4c..4c+3 as packed f32x2 (2x LDS.128)
            ulonglong2 w0 = *(const ulonglong2*)(Ws + (d + 0) * DIM + c * 4);
            ulonglong2 w1 = *(const ulonglong2*)(Ws + (d + 1) * DIM + c * 4);
            #pragma unroll
            for (int i = 0; i < 4; i++) {
                // {dup(a_d), dup(a_{d+1})} in one LDS.128
                ulonglong2 a = *(const ulonglong2*)(As2 + (g * 4 + i) * DIM + d);
                fma2(acc[i][0], a.x, w0.x);
                fma2(acc[i][1], a.x, w0.y);
                fma2(acc[i][0], a.y, w1.x);
                fma2(acc[i][1], a.y, w1.y);
            }
        }

        #pragma unroll
        for (int i = 0; i < 4; i++) {
            int gi = item0 + g * 4 + i;
            if (gi < NUM_ITEMS) {
                float2 p0 = unpack2(acc[i][0]);
                float2 p1 = unpack2(acc[i][1]);
                __half2 h0 = __floats2half2_rn(p0.x, p0.y);
                __half2 h1 = __floats2half2_rn(p1.x, p1.y);
                uint2 st;
                st.x = *(unsigned int*)&h0;
                st.y = *(unsigned int*)&h1;
                *(uint2*)(g_Ti + ((size_t)gi * NUM_REL + r) * DIM + c * 4) = st;
            }
        }
    }
}

// ---------------------------------------------------------------------------
// Edge kernel: 8 lanes per edge, each lane owns 8 halves (one uint4).
// out[e][r] = dot(u[user], Ti[item][r]) + bi[item][r]
// ---------------------------------------------------------------------------
__device__ __forceinline__ float dot8h(uint4 a, uint4 b) {
    float2 a0 = __half22float2(*(const __half2*)&a.x);
    float2 b0 = __half22float2(*(const __half2*)&b.x);
    float2 a1 = __half22float2(*(const __half2*)&a.y);
    float2 b1 = __half22float2(*(const __half2*)&b.y);
    float2 a2 = __half22float2(*(const __half2*)&a.z);
    float2 b2 = __half22float2(*(const __half2*)&b.z);
    float2 a3 = __half22float2(*(const __half2*)&a.w);
    float2 b3 = __half22float2(*(const __half2*)&b.w);
    float s = a0.x * b0.x;
    s = fmaf(a0.y, b0.y, s);
    s = fmaf(a1.x, b1.x, s);
    s = fmaf(a1.y, b1.y, s);
    s = fmaf(a2.x, b2.x, s);
    s = fmaf(a2.y, b2.y, s);
    s = fmaf(a3.x, b3.x, s);
    s = fmaf(a3.y, b3.y, s);
    return s;
}

__global__ void edge_kernel(const void* __restrict__ edge_u,
                            const void* __restrict__ edge_i,
                            float* __restrict__ out,
                            int E) {
    int gid = blockIdx.x * blockDim.x + threadIdx.x;
    int e  = gid >> 3;
    int sl = gid & 7;
    if (e >= E) return;

    long long user, item;
    if (g_idx64) {
        user = __ldg((const long long*)edge_u + e);
        item = __ldg((const long long*)edge_i + e);
    } else {
        user = (long long)__ldg((const int*)edge_u + e);
        item = (long long)__ldg((const int*)edge_i + e);
    }

    uint4 uv = __ldg((const uint4*)g_uh + (size_t)user * 8 + sl);
    const uint4* trow = (const uint4*)g_Ti + (size_t)item * (NUM_REL * 8);

    float a0 = dot8h(uv, __ldg(trow + 0 * 8 + sl));
    float a1 = dot8h(uv, __ldg(trow + 1 * 8 + sl));
    float a2 = dot8h(uv, __ldg(trow + 2 * 8 + sl));
    float a3 = dot8h(uv, __ldg(trow + 3 * 8 + sl));
    float a4 = dot8h(uv, __ldg(trow + 4 * 8 + sl));

    #pragma unroll
    for (int off = 4; off > 0; off >>= 1) {
        a0 += __shfl_xor_sync(0xffffffffu, a0, off);
        a1 += __shfl_xor_sync(0xffffffffu, a1, off);
        a2 += __shfl_xor_sync(0xffffffffu, a2, off);
        a3 += __shfl_xor_sync(0xffffffffu, a3, off);
        a4 += __shfl_xor_sync(0xffffffffu, a4, off);
    }

    if (sl < NUM_REL) {
        float v = (sl == 0) ? a0 : (sl == 1) ? a1 : (sl == 2) ? a2
                : (sl == 3) ? a3 : a4;
        v += __ldg(g_bi + (size_t)item * 8 + sl);
        out[(size_t)e * NUM_REL + sl] = v;
    }
}

// ---------------------------------------------------------------------------
extern "C" void kernel_launch(void* const* d_in, const int* in_sizes, int n_in,
                              void* d_out, int out_size) {
    const float* uf  = (const float*)d_in[0];
    const float* itf = (const float*)d_in[1];
    const void*  eu  = d_in[2];
    const void*  ei  = d_in[3];
    const float* W   = (const float*)d_in[4];
    const float* b   = (const float*)d_in[5];
    int E = in_sizes[2];

    {
        size_t n = (size_t)NUM_USERS * DIM / 2;
        uconv_kernel<<<(unsigned)((n + 255) / 256), 256>>>(uf, eu);
    }

    {
        int blocks = (NUM_ITEMS + TILE_ITEMS - 1) / TILE_ITEMS;
        precompute_kernel<<<blocks, 256>>>(itf, W, b);
    }

    long long total_threads = (long long)E * 8;
    int eblocks = (int)((total_threads + 255) / 256);
    edge_kernel<<<eblocks, 256>>>(eu, ei, (float*)d_out, E);
}